// round 5
// baseline (speedup 1.0000x reference)
#include <cuda_runtime.h>
#include <cuda_fp16.h>
#include <stdint.h>
#include <math.h>

// Problem constants
#define B_   32
#define Q_   20
#define T_   100
#define KDIM 512          // D == H == 512 (GEMM K dim)
#define H_   512
#define N_   (B_*Q_)      // 640 sequences
#define G_   (4*H_)       // 2048 gate columns (interleaved: jp = h*4 + gate)
#define M_   (N_*T_)      // 64000 rows of the x_gates GEMM

#define LDS_   40         // padded smem row stride (fp16 elems): conflict-free ldmatrix
#define CH     32         // k-chunk
#define NCHUNK (KDIM/CH)  // 16

#define NCTA_STEP 160     // persistent grid (16 j-blocks x 10 n-blocks)

// ---------------------------------------------------------------------------
// Static device scratch
// ---------------------------------------------------------------------------
__device__ __align__(16) float  g_xg[(size_t)M_ * G_];      // interleaved gate pre-acts (fp32)
__device__ __align__(16) __half gX_hi[(size_t)M_ * KDIM];
__device__ __align__(16) __half gX_lo[(size_t)M_ * KDIM];
__device__ __align__(16) __half gWih_hi[(size_t)G_ * KDIM]; // interleaved rows
__device__ __align__(16) __half gWih_lo[(size_t)G_ * KDIM];
__device__ __align__(16) __half gWhh_hi[(size_t)G_ * KDIM]; // interleaved rows
__device__ __align__(16) __half gWhh_lo[(size_t)G_ * KDIM];
__device__ float g_biasI[G_];                               // interleaved bih+bhh
__device__ __align__(16) __half g_h_hi[2][(size_t)N_ * H_];
__device__ __align__(16) __half g_h_lo[2][(size_t)N_ * H_];
__device__ float g_c[(size_t)N_ * H_];
__device__ unsigned g_arrive;                               // grid barrier counter

// ---------------------------------------------------------------------------
// PTX helpers (baseline compute_103-safe: cp.async / ldmatrix / mma.sync)
// ---------------------------------------------------------------------------
__device__ __forceinline__ uint32_t smem_u32_of(const void* p) {
    uint32_t a;
    asm("{ .reg .u64 t; cvta.to.shared.u64 t, %1; cvt.u32.u64 %0, t; }" : "=r"(a) : "l"(p));
    return a;
}

__device__ __forceinline__ void cp16(uint32_t dst, const void* src) {
    asm volatile("cp.async.cg.shared.global [%0], [%1], 16;" :: "r"(dst), "l"(src));
}
__device__ __forceinline__ void cp_commit() {
    asm volatile("cp.async.commit_group;" ::: "memory");
}
template<int NN> __device__ __forceinline__ void cp_wait() {
    asm volatile("cp.async.wait_group %0;" :: "n"(NN) : "memory");
}

__device__ __forceinline__ void ldm4(uint32_t addr, uint32_t* r) {
    asm volatile("ldmatrix.sync.aligned.m8n8.x4.shared.b16 {%0,%1,%2,%3}, [%4];"
        : "=r"(r[0]), "=r"(r[1]), "=r"(r[2]), "=r"(r[3]) : "r"(addr));
}

__device__ __forceinline__ void mma16816(float* c, const uint32_t* a, const uint32_t* b) {
    asm volatile("mma.sync.aligned.m16n8k16.row.col.f32.f16.f16.f32 "
        "{%0,%1,%2,%3}, {%4,%5,%6,%7}, {%8,%9}, {%0,%1,%2,%3};"
        : "+f"(c[0]), "+f"(c[1]), "+f"(c[2]), "+f"(c[3])
        : "r"(a[0]), "r"(a[1]), "r"(a[2]), "r"(a[3]), "r"(b[0]), "r"(b[1]));
}

__device__ __forceinline__ void f2split(float x, __half& hi, __half& lo) {
    hi = __float2half_rn(x);
    lo = __float2half_rn(x - __half2float(hi));
}

// ---------------------------------------------------------------------------
// cp.async chunk loader: A is [MT x 512] (hi/lo), B is [128 x 512] (hi/lo).
// smem buffer layout (fp16 elems): Ahi[MT*40] Alo[MT*40] Bhi[128*40] Blo[128*40]
// ---------------------------------------------------------------------------
template<int MT>
__device__ __forceinline__ void load_chunk(
    uint32_t sbase,   // byte addr of buffer start
    const __half* __restrict__ Ah, const __half* __restrict__ Al,
    const __half* __restrict__ Bh, const __half* __restrict__ Bl,
    int kc, int tid)
{
    #pragma unroll
    for (int u = tid; u < MT * 4; u += 256) {
        int r = u >> 2, c = (u & 3) * 8;
        uint32_t d = sbase + (uint32_t)(r * LDS_ + c) * 2;
        const size_t go = (size_t)r * KDIM + kc + c;
        cp16(d,                 Ah + go);
        cp16(d + MT * LDS_ * 2, Al + go);
    }
    #pragma unroll
    for (int u = tid; u < 128 * 4; u += 256) {
        int r = u >> 2, c = (u & 3) * 8;
        uint32_t d = sbase + (uint32_t)(2 * MT * LDS_ + r * LDS_ + c) * 2;
        const size_t go = (size_t)r * KDIM + kc + c;
        cp16(d,                  Bh + go);
        cp16(d + 128 * LDS_ * 2, Bl + go);
    }
}

// ---------------------------------------------------------------------------
// Shared mainloop. MI = m16-frags per warp (2 -> MT=64, 4 -> MT=128).
// S = pipeline stages. 8 warps: 2 (m) x 4 (n). N-tile fixed at 128.
// Split-precision: hi*hi + hi*lo + lo*hi, fp32 accum.
// Uniform group accounting: one commit per loop iter (possibly empty).
// ---------------------------------------------------------------------------
template<int MI, int S>
__device__ __forceinline__ void mma_mainloop(
    uint32_t sb,
    const __half* __restrict__ Ah, const __half* __restrict__ Al,
    const __half* __restrict__ Bh, const __half* __restrict__ Bl,
    float acc[MI][4][4], int tid)
{
    const int MT = MI * 32;
    const int STAGE_B = (2 * MT * LDS_ + 2 * 128 * LDS_) * 2;
    const int lane = tid & 31, wid = tid >> 5;
    const int mw = (wid & 1) * (MI * 16);
    const int nw = (wid >> 1) * 32;

    const int a_row = mw + (lane & 15);
    const int a_col = (lane >> 4) * 8;
    const int b_row = nw + ((lane >> 4) << 3) + (lane & 7);
    const int b_col = ((lane >> 3) & 1) * 8;

    // prologue: stages 0..S-2
    #pragma unroll
    for (int p = 0; p < S - 1; ++p) {
        load_chunk<MT>(sb + p * STAGE_B, Ah, Al, Bh, Bl, p * CH, tid);
        cp_commit();
    }

    #pragma unroll 1
    for (int c = 0; c < NCHUNK; ++c) {
        // issue chunk c+S-1 (or empty group to keep accounting uniform)
        if (c + S - 1 < NCHUNK)
            load_chunk<MT>(sb + ((c + S - 1) % S) * STAGE_B, Ah, Al, Bh, Bl,
                           (c + S - 1) * CH, tid);
        cp_commit();
        cp_wait<S - 1>();            // chunk c complete
        __syncthreads();

        const uint32_t base = sb + (c % S) * STAGE_B;
        #pragma unroll
        for (int kk = 0; kk < CH; kk += 16) {
            uint32_t ra[MI][4], rl[MI][4];
            uint32_t rbh[2][4], rbl[2][4];
            #pragma unroll
            for (int mi = 0; mi < MI; ++mi) {
                uint32_t aaddr = base + (uint32_t)((a_row + mi * 16) * LDS_ + kk + a_col) * 2;
                ldm4(aaddr, ra[mi]);
                ldm4(aaddr + MT * LDS_ * 2, rl[mi]);
            }
            #pragma unroll
            for (int nj = 0; nj < 2; ++nj) {
                uint32_t baddr = base + (uint32_t)(2 * MT * LDS_ + (b_row + nj * 16) * LDS_ + kk + b_col) * 2;
                ldm4(baddr, rbh[nj]);
                ldm4(baddr + 128 * LDS_ * 2, rbl[nj]);
            }
            #pragma unroll
            for (int mi = 0; mi < MI; ++mi) {
                #pragma unroll
                for (int b8 = 0; b8 < 4; ++b8) {
                    const uint32_t* bh = &rbh[b8 >> 1][(b8 & 1) * 2];
                    const uint32_t* bl = &rbl[b8 >> 1][(b8 & 1) * 2];
                    mma16816(acc[mi][b8], ra[mi], bh);   // hi*hi
                    mma16816(acc[mi][b8], ra[mi], bl);   // hi*lo
                    mma16816(acc[mi][b8], rl[mi], bh);   // lo*hi
                }
            }
        }
        __syncthreads();   // buffer-reuse guard (iter c+1 writes buf (c+S-1)%S == old)
    }
}

// ---------------------------------------------------------------------------
// Setup kernels
// ---------------------------------------------------------------------------
__global__ void init_state_kernel() {
    int idx = blockIdx.x * blockDim.x + threadIdx.x;
    if (idx == 0) g_arrive = 0u;
    if (idx < N_ * H_) {
        g_h_hi[0][idx] = __float2half_rn(0.0f);
        g_h_lo[0][idx] = __float2half_rn(0.0f);
        g_c[idx] = 0.0f;
    }
}

__global__ void conv_x_kernel(const float* __restrict__ X) {
    size_t base = ((size_t)blockIdx.x * blockDim.x + threadIdx.x) * 4;
    if (base < (size_t)M_ * KDIM) {
        float4 v = *(const float4*)(X + base);
        __half h0, l0, h1, l1, h2, l2, h3, l3;
        f2split(v.x, h0, l0); f2split(v.y, h1, l1);
        f2split(v.z, h2, l2); f2split(v.w, h3, l3);
        gX_hi[base + 0] = h0; gX_hi[base + 1] = h1; gX_hi[base + 2] = h2; gX_hi[base + 3] = h3;
        gX_lo[base + 0] = l0; gX_lo[base + 1] = l1; gX_lo[base + 2] = l2; gX_lo[base + 3] = l3;
    }
}

__global__ void conv_w_kernel(const float* __restrict__ Wih,
                              const float* __restrict__ Whh,
                              const float* __restrict__ bih,
                              const float* __restrict__ bhh) {
    int jp = blockIdx.x;                 // interleaved dst row 0..2047
    int gate = jp & 3, h = jp >> 2;
    int j = gate * H_ + h;               // source row
    const float* si = Wih + (size_t)j * KDIM;
    const float* sh = Whh + (size_t)j * KDIM;
    for (int k = threadIdx.x; k < KDIM; k += blockDim.x) {
        __half hi, lo;
        f2split(si[k], hi, lo);
        gWih_hi[(size_t)jp * KDIM + k] = hi; gWih_lo[(size_t)jp * KDIM + k] = lo;
        f2split(sh[k], hi, lo);
        gWhh_hi[(size_t)jp * KDIM + k] = hi; gWhh_lo[(size_t)jp * KDIM + k] = lo;
    }
    if (threadIdx.x == 0) g_biasI[jp] = bih[j] + bhh[j];
}

// ---------------------------------------------------------------------------
// x_gates GEMM: 128x128 tile, grid (16, 500), 4-stage pipeline.
// ---------------------------------------------------------------------------
#define XG_STAGE ((2*128*LDS_ + 2*128*LDS_) * 2)         // 40960 B
#define XG_SMEM  (XG_STAGE * 4)                          // 163840 B

__global__ __launch_bounds__(256, 1)
void xg_mma_kernel() {
    extern __shared__ __half smem[];
    const uint32_t sb = smem_u32_of(smem);
    __shared__ float bias_s[128];
    const int tid = threadIdx.x;
    const int j0 = blockIdx.x * 128;
    const int m0 = blockIdx.y * 128;
    if (tid < 128) bias_s[tid] = g_biasI[j0 + tid];

    float acc[4][4][4];
    #pragma unroll
    for (int a = 0; a < 4; ++a)
        #pragma unroll
        for (int b = 0; b < 4; ++b)
            #pragma unroll
            for (int d = 0; d < 4; ++d) acc[a][b][d] = 0.0f;

    mma_mainloop<4, 4>(sb,
        gX_hi   + (size_t)m0 * KDIM, gX_lo   + (size_t)m0 * KDIM,
        gWih_hi + (size_t)j0 * KDIM, gWih_lo + (size_t)j0 * KDIM,
        acc, tid);

    const int lane = tid & 31, wid = tid >> 5;
    const int mw = (wid & 1) * 64, nw = (wid >> 1) * 32;
    #pragma unroll
    for (int mi = 0; mi < 4; ++mi) {
        #pragma unroll
        for (int h2 = 0; h2 < 2; ++h2) {
            const int r = m0 + mw + mi * 16 + (lane >> 2) + h2 * 8;
            float* dst = g_xg + (size_t)r * G_ + j0;
            #pragma unroll
            for (int ni = 0; ni < 4; ++ni) {
                const int cc = nw + ni * 8 + (lane & 3) * 2;
                float2 v = make_float2(acc[mi][ni][h2 * 2 + 0] + bias_s[cc],
                                       acc[mi][ni][h2 * 2 + 1] + bias_s[cc + 1]);
                *(float2*)(dst + cc) = v;
            }
        }
    }
}

// ---------------------------------------------------------------------------
// Persistent recurrent kernel: 160 CTAs run all 100 steps, grid barrier/step.
// Per-CTA tile: 64 seqs x 128 gate-cols (= 32 h x 4 gates). 3-stage pipeline.
// __launch_bounds__(256,2): regs<=128 + smem 92KB/CTA -> 2 CTAs/SM guaranteed
// co-resident (160 <= 296), so the spin barrier is safe.
// ---------------------------------------------------------------------------
#define STEP_STAGE ((2*64*LDS_ + 2*128*LDS_) * 2)        // 30720 B
#define STEP_SMEM  (STEP_STAGE * 3)                      // 92160 B

__device__ __forceinline__ void grid_barrier(int tid, unsigned target) {
    __threadfence();          // release this CTA's h/c writes
    __syncthreads();          // all threads of CTA fenced
    if (tid == 0) {
        atomicAdd(&g_arrive, 1u);
        unsigned v;
        do {
            asm volatile("ld.volatile.global.u32 %0, [%1];" : "=r"(v) : "l"(&g_arrive));
        } while (v < target);
        __threadfence();      // acquire
    }
    __syncthreads();
}

__global__ __launch_bounds__(256, 2)
void lstm_persistent_kernel(float* __restrict__ out) {
    extern __shared__ __half smem[];
    const uint32_t sb = smem_u32_of(smem);
    const int tid = threadIdx.x;
    const int j0 = blockIdx.x * 128;     // interleaved gate-col base
    const int hb = blockIdx.x * 32;      // h-column base
    const int n0 = blockIdx.y * 64;      // sequence-row base
    const int lane = tid & 31, wid = tid >> 5;
    const int mw = (wid & 1) * 32, nw = (wid >> 1) * 32;
    float* Cs = (float*)smem;

    #pragma unroll 1
    for (int t = 0; t < T_; ++t) {
        const int cur = t & 1, nxt = cur ^ 1;

        float acc[2][4][4];
        #pragma unroll
        for (int a = 0; a < 2; ++a)
            #pragma unroll
            for (int b = 0; b < 4; ++b)
                #pragma unroll
                for (int d = 0; d < 4; ++d) acc[a][b][d] = 0.0f;

        mma_mainloop<2, 3>(sb,
            g_h_hi[cur] + (size_t)n0 * H_, g_h_lo[cur] + (size_t)n0 * H_,
            gWhh_hi + (size_t)j0 * KDIM,   gWhh_lo + (size_t)j0 * KDIM,
            acc, tid);

        // stage C tile [64][128] (stride 132) in smem (reuses pipeline buffers)
        #pragma unroll
        for (int mi = 0; mi < 2; ++mi) {
            #pragma unroll
            for (int ni = 0; ni < 4; ++ni) {
                const int r = mw + mi * 16 + (lane >> 2);
                const int c = nw + ni * 8 + (lane & 3) * 2;
                *(float2*)&Cs[r * 132 + c]       = make_float2(acc[mi][ni][0], acc[mi][ni][1]);
                *(float2*)&Cs[(r + 8) * 132 + c] = make_float2(acc[mi][ni][2], acc[mi][ni][3]);
            }
        }
        __syncthreads();

        // fused LSTM cell update
        const bool last = (t == T_ - 1);
        const int hl = tid & 31;
        #pragma unroll
        for (int e = 0; e < 8; ++e) {
            const int nr = (tid >> 5) + e * 8;
            const int gn = n0 + nr;
            float4 cg = *(const float4*)&Cs[nr * 132 + hl * 4];
            float4 xv = *(const float4*)(g_xg + ((size_t)gn * T_ + t) * G_ + j0 + hl * 4);
            float ig = cg.x + xv.x, fg = cg.y + xv.y;
            float gg = cg.z + xv.z, og = cg.w + xv.w;

            float is = 1.0f / (1.0f + expf(-ig));
            float fs = 1.0f / (1.0f + expf(-fg));
            float gt = tanhf(gg);
            float os = 1.0f / (1.0f + expf(-og));

            const size_t ci = (size_t)gn * H_ + hb + hl;
            float c = fs * g_c[ci] + is * gt;
            g_c[ci] = c;
            float hv = os * tanhf(c);
            if (last) {
                out[ci] = hv;
            } else {
                __half hi, lo;
                f2split(hv, hi, lo);
                g_h_hi[nxt][ci] = hi;
                g_h_lo[nxt][ci] = lo;
            }
        }

        // grid-wide barrier (also guards smem reuse for next iteration)
        grid_barrier(tid, (unsigned)NCTA_STEP * (unsigned)(t + 1));
    }
}

// ---------------------------------------------------------------------------
// Launch
// ---------------------------------------------------------------------------
extern "C" void kernel_launch(void* const* d_in, const int* in_sizes, int n_in,
                              void* d_out, int out_size)
{
    const float* X   = (const float*)d_in[0];   // [B,Q,T,D] == [N*T, D]
    const float* Wih = (const float*)d_in[1];   // [4H, D]
    const float* Whh = (const float*)d_in[2];   // [4H, H]
    const float* bih = (const float*)d_in[3];   // [4H]
    const float* bhh = (const float*)d_in[4];   // [4H]
    float* out = (float*)d_out;                 // [B,Q,H] == [N, H]

    cudaFuncSetAttribute(xg_mma_kernel,          cudaFuncAttributeMaxDynamicSharedMemorySize, XG_SMEM);
    cudaFuncSetAttribute(lstm_persistent_kernel, cudaFuncAttributeMaxDynamicSharedMemorySize, STEP_SMEM);

    init_state_kernel<<<(N_ * H_ + 255) / 256, 256>>>();
    conv_x_kernel<<<(int)(((size_t)M_ * KDIM / 4 + 255) / 256), 256>>>(X);
    conv_w_kernel<<<G_, 256>>>(Wih, Whh, bih, bhh);

    xg_mma_kernel<<<dim3(G_ / 128, M_ / 128), 256, XG_SMEM>>>();

    lstm_persistent_kernel<<<dim3(G_ / 128, N_ / 64), 256, STEP_SMEM>>>(out);
}

// round 6
// speedup vs baseline: 1.1875x; 1.1875x over previous
#include <cuda_runtime.h>
#include <cuda_fp16.h>
#include <stdint.h>
#include <math.h>

// Problem constants
#define B_   32
#define Q_   20
#define T_   100
#define KDIM 512          // D == H == 512 (GEMM K dim)
#define H_   512
#define N_   (B_*Q_)      // 640 sequences
#define G_   (4*H_)       // 2048 gate columns (interleaved: jp = h*4 + gate)
#define M_   (N_*T_)      // 64000 rows of the x_gates GEMM

#define LDS_   40         // padded smem row stride (fp16 elems): conflict-free ldmatrix
#define CH     32         // k-chunk
#define NCHUNK (KDIM/CH)  // 16

// ---------------------------------------------------------------------------
// Static device scratch
// ---------------------------------------------------------------------------
__device__ __align__(16) float  g_xg[(size_t)M_ * G_];      // interleaved gate pre-acts (fp32)
__device__ __align__(16) __half gX_hi[(size_t)M_ * KDIM];
__device__ __align__(16) __half gX_lo[(size_t)M_ * KDIM];
__device__ __align__(16) __half gWih_hi[(size_t)G_ * KDIM]; // interleaved rows
__device__ __align__(16) __half gWih_lo[(size_t)G_ * KDIM];
__device__ __align__(16) __half gWhh_hi[(size_t)G_ * KDIM]; // interleaved rows
__device__ __align__(16) __half gWhh_lo[(size_t)G_ * KDIM];
__device__ float g_biasI[G_];                               // interleaved bih+bhh
__device__ __align__(16) __half g_h_hi[2][(size_t)N_ * H_];
__device__ __align__(16) __half g_h_lo[2][(size_t)N_ * H_];
__device__ float g_c[(size_t)N_ * H_];

// ---------------------------------------------------------------------------
// PTX helpers (baseline compute_103-safe: cp.async / ldmatrix / mma.sync)
// ---------------------------------------------------------------------------
__device__ __forceinline__ uint32_t smem_u32_of(const void* p) {
    uint32_t a;
    asm("{ .reg .u64 t; cvta.to.shared.u64 t, %1; cvt.u32.u64 %0, t; }" : "=r"(a) : "l"(p));
    return a;
}

__device__ __forceinline__ void cp16(uint32_t dst, const void* src) {
    asm volatile("cp.async.cg.shared.global [%0], [%1], 16;" :: "r"(dst), "l"(src));
}
__device__ __forceinline__ void cp_commit() {
    asm volatile("cp.async.commit_group;" ::: "memory");
}
template<int NN> __device__ __forceinline__ void cp_wait() {
    asm volatile("cp.async.wait_group %0;" :: "n"(NN) : "memory");
}

__device__ __forceinline__ void ldm4(uint32_t addr, uint32_t* r) {
    asm volatile("ldmatrix.sync.aligned.m8n8.x4.shared.b16 {%0,%1,%2,%3}, [%4];"
        : "=r"(r[0]), "=r"(r[1]), "=r"(r[2]), "=r"(r[3]) : "r"(addr));
}

__device__ __forceinline__ void mma16816(float* c, const uint32_t* a, const uint32_t* b) {
    asm volatile("mma.sync.aligned.m16n8k16.row.col.f32.f16.f16.f32 "
        "{%0,%1,%2,%3}, {%4,%5,%6,%7}, {%8,%9}, {%0,%1,%2,%3};"
        : "+f"(c[0]), "+f"(c[1]), "+f"(c[2]), "+f"(c[3])
        : "r"(a[0]), "r"(a[1]), "r"(a[2]), "r"(a[3]), "r"(b[0]), "r"(b[1]));
}

__device__ __forceinline__ void f2split(float x, __half& hi, __half& lo) {
    hi = __float2half_rn(x);
    lo = __float2half_rn(x - __half2float(hi));
}

// ---------------------------------------------------------------------------
// cp.async chunk loader: A is [MT x 512] (hi/lo), B is [NT x 512] (hi/lo).
// smem buffer layout (fp16 elems): Ahi[MT*40] Alo[MT*40] Bhi[NT*40] Blo[NT*40]
// ---------------------------------------------------------------------------
template<int MT, int NT>
__device__ __forceinline__ void load_chunk(
    uint32_t sbase,   // byte addr of buffer start
    const __half* __restrict__ Ah, const __half* __restrict__ Al,
    const __half* __restrict__ Bh, const __half* __restrict__ Bl,
    int kc, int tid)
{
    #pragma unroll
    for (int u = tid; u < MT * 4; u += 256) {
        int r = u >> 2, c = (u & 3) * 8;
        uint32_t d = sbase + (uint32_t)(r * LDS_ + c) * 2;
        const size_t go = (size_t)r * KDIM + kc + c;
        cp16(d,                 Ah + go);
        cp16(d + MT * LDS_ * 2, Al + go);
    }
    #pragma unroll
    for (int u = tid; u < NT * 4; u += 256) {
        int r = u >> 2, c = (u & 3) * 8;
        uint32_t d = sbase + (uint32_t)(2 * MT * LDS_ + r * LDS_ + c) * 2;
        const size_t go = (size_t)r * KDIM + kc + c;
        cp16(d,                 Bh + go);
        cp16(d + NT * LDS_ * 2, Bl + go);
    }
}

// ---------------------------------------------------------------------------
// Shared mainloop. MI = m16-frags per warp (MT = MI*32, 2 warps along m).
// NJ = n16-frags per warp (NT = NJ*64, 4 warps along n). S = pipeline stages.
// Split-precision: hi*hi + hi*lo + lo*hi, fp32 accum.
// Uniform cp.async group accounting: one commit per loop iter (maybe empty).
// ---------------------------------------------------------------------------
template<int MI, int NJ, int S>
__device__ __forceinline__ void mma_mainloop(
    uint32_t sb,
    const __half* __restrict__ Ah, const __half* __restrict__ Al,
    const __half* __restrict__ Bh, const __half* __restrict__ Bl,
    float acc[MI][NJ * 2][4], int tid)
{
    const int MT = MI * 32;
    const int NT = NJ * 64;
    const int STAGE_B = (2 * MT * LDS_ + 2 * NT * LDS_) * 2;
    const int lane = tid & 31, wid = tid >> 5;
    const int mw = (wid & 1) * (MI * 16);
    const int nw = (wid >> 1) * (NJ * 16);

    const int a_row = mw + (lane & 15);
    const int a_col = (lane >> 4) * 8;
    const int b_row = nw + ((lane >> 4) << 3) + (lane & 7);
    const int b_col = ((lane >> 3) & 1) * 8;

    // prologue: stages 0..S-2
    #pragma unroll
    for (int p = 0; p < S - 1; ++p) {
        load_chunk<MT, NT>(sb + p * STAGE_B, Ah, Al, Bh, Bl, p * CH, tid);
        cp_commit();
    }

    #pragma unroll 1
    for (int c = 0; c < NCHUNK; ++c) {
        if (c + S - 1 < NCHUNK)
            load_chunk<MT, NT>(sb + ((c + S - 1) % S) * STAGE_B, Ah, Al, Bh, Bl,
                               (c + S - 1) * CH, tid);
        cp_commit();
        cp_wait<S - 1>();            // chunk c complete
        __syncthreads();

        const uint32_t base = sb + (c % S) * STAGE_B;
        #pragma unroll
        for (int kk = 0; kk < CH; kk += 16) {
            uint32_t ra[MI][4], rl[MI][4];
            uint32_t rbh[NJ][4], rbl[NJ][4];
            #pragma unroll
            for (int mi = 0; mi < MI; ++mi) {
                uint32_t aaddr = base + (uint32_t)((a_row + mi * 16) * LDS_ + kk + a_col) * 2;
                ldm4(aaddr, ra[mi]);
                ldm4(aaddr + MT * LDS_ * 2, rl[mi]);
            }
            #pragma unroll
            for (int nj = 0; nj < NJ; ++nj) {
                uint32_t baddr = base + (uint32_t)(2 * MT * LDS_ + (b_row + nj * 16) * LDS_ + kk + b_col) * 2;
                ldm4(baddr, rbh[nj]);
                ldm4(baddr + NT * LDS_ * 2, rbl[nj]);
            }
            #pragma unroll
            for (int mi = 0; mi < MI; ++mi) {
                #pragma unroll
                for (int b8 = 0; b8 < NJ * 2; ++b8) {
                    const uint32_t* bh = &rbh[b8 >> 1][(b8 & 1) * 2];
                    const uint32_t* bl = &rbl[b8 >> 1][(b8 & 1) * 2];
                    mma16816(acc[mi][b8], ra[mi], bh);   // hi*hi
                    mma16816(acc[mi][b8], ra[mi], bl);   // hi*lo
                    mma16816(acc[mi][b8], rl[mi], bh);   // lo*hi
                }
            }
        }
        __syncthreads();   // buffer-reuse guard
    }
}

// ---------------------------------------------------------------------------
// Setup kernels
// ---------------------------------------------------------------------------
__global__ void init_state_kernel() {
    int idx = blockIdx.x * blockDim.x + threadIdx.x;
    if (idx < N_ * H_) {
        g_h_hi[0][idx] = __float2half_rn(0.0f);
        g_h_lo[0][idx] = __float2half_rn(0.0f);
        g_c[idx] = 0.0f;
    }
}

__global__ void conv_x_kernel(const float* __restrict__ X) {
    size_t base = ((size_t)blockIdx.x * blockDim.x + threadIdx.x) * 4;
    if (base < (size_t)M_ * KDIM) {
        float4 v = *(const float4*)(X + base);
        __half h0, l0, h1, l1, h2, l2, h3, l3;
        f2split(v.x, h0, l0); f2split(v.y, h1, l1);
        f2split(v.z, h2, l2); f2split(v.w, h3, l3);
        gX_hi[base + 0] = h0; gX_hi[base + 1] = h1; gX_hi[base + 2] = h2; gX_hi[base + 3] = h3;
        gX_lo[base + 0] = l0; gX_lo[base + 1] = l1; gX_lo[base + 2] = l2; gX_lo[base + 3] = l3;
    }
}

__global__ void conv_w_kernel(const float* __restrict__ Wih,
                              const float* __restrict__ Whh,
                              const float* __restrict__ bih,
                              const float* __restrict__ bhh) {
    int jp = blockIdx.x;                 // interleaved dst row 0..2047
    int gate = jp & 3, h = jp >> 2;
    int j = gate * H_ + h;               // source row
    const float* si = Wih + (size_t)j * KDIM;
    const float* sh = Whh + (size_t)j * KDIM;
    for (int k = threadIdx.x; k < KDIM; k += blockDim.x) {
        __half hi, lo;
        f2split(si[k], hi, lo);
        gWih_hi[(size_t)jp * KDIM + k] = hi; gWih_lo[(size_t)jp * KDIM + k] = lo;
        f2split(sh[k], hi, lo);
        gWhh_hi[(size_t)jp * KDIM + k] = hi; gWhh_lo[(size_t)jp * KDIM + k] = lo;
    }
    if (threadIdx.x == 0) g_biasI[jp] = bih[j] + bhh[j];
}

// ---------------------------------------------------------------------------
// x_gates GEMM: 128x128 tile, grid (16, 500), 2-stage, 2 CTAs/SM target.
// ---------------------------------------------------------------------------
#define XG_STAGE ((2*128*LDS_ + 2*128*LDS_) * 2)         // 40960 B
#define XG_SMEM  (XG_STAGE * 2)                          // 81920 B

__global__ __launch_bounds__(256, 2)
void xg_mma_kernel() {
    extern __shared__ __half smem[];
    const uint32_t sb = smem_u32_of(smem);
    __shared__ float bias_s[128];
    const int tid = threadIdx.x;
    const int j0 = blockIdx.x * 128;
    const int m0 = blockIdx.y * 128;
    if (tid < 128) bias_s[tid] = g_biasI[j0 + tid];

    float acc[4][4][4];
    #pragma unroll
    for (int a = 0; a < 4; ++a)
        #pragma unroll
        for (int b = 0; b < 4; ++b)
            #pragma unroll
            for (int d = 0; d < 4; ++d) acc[a][b][d] = 0.0f;

    mma_mainloop<4, 2, 2>(sb,
        gX_hi   + (size_t)m0 * KDIM, gX_lo   + (size_t)m0 * KDIM,
        gWih_hi + (size_t)j0 * KDIM, gWih_lo + (size_t)j0 * KDIM,
        acc, tid);

    const int lane = tid & 31, wid = tid >> 5;
    const int mw = (wid & 1) * 64, nw = (wid >> 1) * 32;
    #pragma unroll
    for (int mi = 0; mi < 4; ++mi) {
        #pragma unroll
        for (int h2 = 0; h2 < 2; ++h2) {
            const int r = m0 + mw + mi * 16 + (lane >> 2) + h2 * 8;
            float* dst = g_xg + (size_t)r * G_ + j0;
            #pragma unroll
            for (int ni = 0; ni < 4; ++ni) {
                const int cc = nw + ni * 8 + (lane & 3) * 2;
                float2 v = make_float2(acc[mi][ni][h2 * 2 + 0] + bias_s[cc],
                                       acc[mi][ni][h2 * 2 + 1] + bias_s[cc + 1]);
                *(float2*)(dst + cc) = v;
            }
        }
    }
}

// ---------------------------------------------------------------------------
// Recurrent step: 64x64 tile (= 64 seqs x 16 h x 4 gates), grid (32, 10) = 320
// CTAs (balanced: worst SM runs 3 small tiles vs 2 big ones before).
// 3-stage pipeline, 2 CTAs/SM. Fused cell update via smem-staged C.
// ---------------------------------------------------------------------------
#define STEP_STAGE ((2*64*LDS_ + 2*64*LDS_) * 2)         // 20480 B
#define STEP_SMEM  (STEP_STAGE * 3)                      // 61440 B

__global__ __launch_bounds__(256, 2)
void step_mma_kernel(float* __restrict__ out, int t) {
    extern __shared__ __half smem[];
    const uint32_t sb = smem_u32_of(smem);
    const int tid = threadIdx.x;
    const int j0 = blockIdx.x * 64;      // interleaved gate-col base
    const int hb = blockIdx.x * 16;      // h-column base
    const int n0 = blockIdx.y * 64;      // sequence-row base
    const int cur = t & 1, nxt = cur ^ 1;

    float acc[2][2][4];
    #pragma unroll
    for (int a = 0; a < 2; ++a)
        #pragma unroll
        for (int b = 0; b < 2; ++b)
            #pragma unroll
            for (int d = 0; d < 4; ++d) acc[a][b][d] = 0.0f;

    mma_mainloop<2, 1, 3>(sb,
        g_h_hi[cur] + (size_t)n0 * H_, g_h_lo[cur] + (size_t)n0 * H_,
        gWhh_hi + (size_t)j0 * KDIM,   gWhh_lo + (size_t)j0 * KDIM,
        acc, tid);

    // stage C tile [64][64] (stride 68) in smem (reuses pipeline buffers)
    float* Cs = (float*)smem;
    const int lane = tid & 31, wid = tid >> 5;
    const int mw = (wid & 1) * 32, nw = (wid >> 1) * 16;
    #pragma unroll
    for (int mi = 0; mi < 2; ++mi) {
        #pragma unroll
        for (int ni = 0; ni < 2; ++ni) {
            const int r = mw + mi * 16 + (lane >> 2);
            const int c = nw + ni * 8 + (lane & 3) * 2;
            *(float2*)&Cs[r * 68 + c]       = make_float2(acc[mi][ni][0], acc[mi][ni][1]);
            *(float2*)&Cs[(r + 8) * 68 + c] = make_float2(acc[mi][ni][2], acc[mi][ni][3]);
        }
    }
    __syncthreads();

    // fused LSTM cell update: 4 cells/thread
    const bool last = (t == T_ - 1);
    const int hl = tid & 15;             // h lane within the 16 h-cols
    #pragma unroll
    for (int e = 0; e < 4; ++e) {
        const int nr = (tid >> 4) + e * 16;
        const int gn = n0 + nr;
        float4 cg = *(const float4*)&Cs[nr * 68 + hl * 4];
        float4 xv = *(const float4*)(g_xg + ((size_t)gn * T_ + t) * G_ + j0 + hl * 4);
        float ig = cg.x + xv.x, fg = cg.y + xv.y;
        float gg = cg.z + xv.z, og = cg.w + xv.w;

        float is = 1.0f / (1.0f + __expf(-ig));
        float fs = 1.0f / (1.0f + __expf(-fg));
        float gt = tanhf(gg);
        float os = 1.0f / (1.0f + __expf(-og));

        const size_t ci = (size_t)gn * H_ + hb + hl;
        float c = fs * g_c[ci] + is * gt;
        g_c[ci] = c;
        float hv = os * tanhf(c);
        if (last) {
            out[ci] = hv;
        } else {
            __half hi, lo;
            f2split(hv, hi, lo);
            g_h_hi[nxt][ci] = hi;
            g_h_lo[nxt][ci] = lo;
        }
    }
}

// ---------------------------------------------------------------------------
// Launch
// ---------------------------------------------------------------------------
extern "C" void kernel_launch(void* const* d_in, const int* in_sizes, int n_in,
                              void* d_out, int out_size)
{
    const float* X   = (const float*)d_in[0];   // [B,Q,T,D] == [N*T, D]
    const float* Wih = (const float*)d_in[1];   // [4H, D]
    const float* Whh = (const float*)d_in[2];   // [4H, H]
    const float* bih = (const float*)d_in[3];   // [4H]
    const float* bhh = (const float*)d_in[4];   // [4H]
    float* out = (float*)d_out;                 // [B,Q,H] == [N, H]

    cudaFuncSetAttribute(xg_mma_kernel,   cudaFuncAttributeMaxDynamicSharedMemorySize, XG_SMEM);
    cudaFuncSetAttribute(step_mma_kernel, cudaFuncAttributeMaxDynamicSharedMemorySize, STEP_SMEM);

    init_state_kernel<<<(N_ * H_ + 255) / 256, 256>>>();
    conv_x_kernel<<<(int)(((size_t)M_ * KDIM / 4 + 255) / 256), 256>>>(X);
    conv_w_kernel<<<G_, 256>>>(Wih, Whh, bih, bhh);

    xg_mma_kernel<<<dim3(G_ / 128, M_ / 128), 256, XG_SMEM>>>();

    for (int t = 0; t < T_; ++t) {
        step_mma_kernel<<<dim3(G_ / 64, N_ / 64), 256, STEP_SMEM>>>(out, t);
    }
}

// round 7
// speedup vs baseline: 1.1893x; 1.0014x over previous
#include <cuda_runtime.h>
#include <cuda_fp16.h>
#include <stdint.h>
#include <math.h>

// Problem constants
#define B_   32
#define Q_   20
#define T_   100
#define KDIM 512          // D == H == 512 (GEMM K dim)
#define H_   512
#define N_   (B_*Q_)      // 640 sequences
#define G_   (4*H_)       // 2048 gate columns (interleaved: jp = h*4 + gate)
#define M_   (N_*T_)      // 64000 rows of the x_gates GEMM

#define LDS_   40         // padded smem row stride (fp16 elems): conflict-free ldmatrix
#define CH     32         // k-chunk
#define NCHUNK (KDIM/CH)  // 16

// Persistent step kernel geometry
#define NCTA_P 128        // 32 j-blocks x 4 n-chunks, 1 CTA/SM (all co-resident)
#define WSTRIDE 520       // W smem row stride (elems): 16B-aligned, conflict-free ldmatrix
#define ROWS_P 160        // sequence rows per CTA
// smem elem offsets (halfs)
#define SM_WHI 0
#define SM_WLO 33280              // 64*520
#define SM_HST 66560              // h stages start (3 x 12800)
#define HSTAGE_E 12800            // per-stage: 160*40 hi + 160*40 lo
#define SMEM_P_BYTES ((SM_HST + 3*HSTAGE_E) * 2)   // 209920 B

// ---------------------------------------------------------------------------
// Static device scratch
// ---------------------------------------------------------------------------
__device__ __align__(16) float  g_xg[(size_t)M_ * G_];      // interleaved gate pre-acts (fp32)
__device__ __align__(16) __half gX_hi[(size_t)M_ * KDIM];
__device__ __align__(16) __half gX_lo[(size_t)M_ * KDIM];
__device__ __align__(16) __half gWih_hi[(size_t)G_ * KDIM]; // interleaved rows
__device__ __align__(16) __half gWih_lo[(size_t)G_ * KDIM];
__device__ __align__(16) __half gWhh_hi[(size_t)G_ * KDIM]; // interleaved rows
__device__ __align__(16) __half gWhh_lo[(size_t)G_ * KDIM];
__device__ float g_biasI[G_];                               // interleaved bih+bhh
__device__ __align__(16) __half g_h_hi[2][(size_t)N_ * H_];
__device__ __align__(16) __half g_h_lo[2][(size_t)N_ * H_];
__device__ float g_c[(size_t)N_ * H_];
__device__ unsigned g_arrive;                               // grid barrier counter

// ---------------------------------------------------------------------------
// PTX helpers (baseline compute_103-safe: cp.async / ldmatrix / mma.sync)
// ---------------------------------------------------------------------------
__device__ __forceinline__ uint32_t smem_u32_of(const void* p) {
    uint32_t a;
    asm("{ .reg .u64 t; cvta.to.shared.u64 t, %1; cvt.u32.u64 %0, t; }" : "=r"(a) : "l"(p));
    return a;
}

__device__ __forceinline__ void cp16(uint32_t dst, const void* src) {
    asm volatile("cp.async.cg.shared.global [%0], [%1], 16;" :: "r"(dst), "l"(src));
}
__device__ __forceinline__ void cp_commit() {
    asm volatile("cp.async.commit_group;" ::: "memory");
}
template<int NN> __device__ __forceinline__ void cp_wait() {
    asm volatile("cp.async.wait_group %0;" :: "n"(NN) : "memory");
}

__device__ __forceinline__ void ldm4(uint32_t addr, uint32_t* r) {
    asm volatile("ldmatrix.sync.aligned.m8n8.x4.shared.b16 {%0,%1,%2,%3}, [%4];"
        : "=r"(r[0]), "=r"(r[1]), "=r"(r[2]), "=r"(r[3]) : "r"(addr));
}

__device__ __forceinline__ void mma16816(float* c, const uint32_t* a, const uint32_t* b) {
    asm volatile("mma.sync.aligned.m16n8k16.row.col.f32.f16.f16.f32 "
        "{%0,%1,%2,%3}, {%4,%5,%6,%7}, {%8,%9}, {%0,%1,%2,%3};"
        : "+f"(c[0]), "+f"(c[1]), "+f"(c[2]), "+f"(c[3])
        : "r"(a[0]), "r"(a[1]), "r"(a[2]), "r"(a[3]), "r"(b[0]), "r"(b[1]));
}

__device__ __forceinline__ void f2split(float x, __half& hi, __half& lo) {
    hi = __float2half_rn(x);
    lo = __float2half_rn(x - __half2float(hi));
}

// ---------------------------------------------------------------------------
// cp.async chunk loader for xg GEMM: A [MT x 512] hi/lo, B [NT x 512] hi/lo.
// ---------------------------------------------------------------------------
template<int MT, int NT>
__device__ __forceinline__ void load_chunk(
    uint32_t sbase,
    const __half* __restrict__ Ah, const __half* __restrict__ Al,
    const __half* __restrict__ Bh, const __half* __restrict__ Bl,
    int kc, int tid)
{
    #pragma unroll
    for (int u = tid; u < MT * 4; u += 256) {
        int r = u >> 2, c = (u & 3) * 8;
        uint32_t d = sbase + (uint32_t)(r * LDS_ + c) * 2;
        const size_t go = (size_t)r * KDIM + kc + c;
        cp16(d,                 Ah + go);
        cp16(d + MT * LDS_ * 2, Al + go);
    }
    #pragma unroll
    for (int u = tid; u < NT * 4; u += 256) {
        int r = u >> 2, c = (u & 3) * 8;
        uint32_t d = sbase + (uint32_t)(2 * MT * LDS_ + r * LDS_ + c) * 2;
        const size_t go = (size_t)r * KDIM + kc + c;
        cp16(d,                 Bh + go);
        cp16(d + NT * LDS_ * 2, Bl + go);
    }
}

// ---------------------------------------------------------------------------
// xg mainloop (as R6). MI m16-frags/warp, NJ n16-frags/warp, S stages.
// ---------------------------------------------------------------------------
template<int MI, int NJ, int S>
__device__ __forceinline__ void mma_mainloop(
    uint32_t sb,
    const __half* __restrict__ Ah, const __half* __restrict__ Al,
    const __half* __restrict__ Bh, const __half* __restrict__ Bl,
    float acc[MI][NJ * 2][4], int tid)
{
    const int MT = MI * 32;
    const int NT = NJ * 64;
    const int STAGE_B = (2 * MT * LDS_ + 2 * NT * LDS_) * 2;
    const int lane = tid & 31, wid = tid >> 5;
    const int mw = (wid & 1) * (MI * 16);
    const int nw = (wid >> 1) * (NJ * 16);

    const int a_row = mw + (lane & 15);
    const int a_col = (lane >> 4) * 8;
    const int b_row = nw + ((lane >> 4) << 3) + (lane & 7);
    const int b_col = ((lane >> 3) & 1) * 8;

    #pragma unroll
    for (int p = 0; p < S - 1; ++p) {
        load_chunk<MT, NT>(sb + p * STAGE_B, Ah, Al, Bh, Bl, p * CH, tid);
        cp_commit();
    }

    #pragma unroll 1
    for (int c = 0; c < NCHUNK; ++c) {
        if (c + S - 1 < NCHUNK)
            load_chunk<MT, NT>(sb + ((c + S - 1) % S) * STAGE_B, Ah, Al, Bh, Bl,
                               (c + S - 1) * CH, tid);
        cp_commit();
        cp_wait<S - 1>();
        __syncthreads();

        const uint32_t base = sb + (c % S) * STAGE_B;
        #pragma unroll
        for (int kk = 0; kk < CH; kk += 16) {
            uint32_t ra[MI][4], rl[MI][4];
            uint32_t rbh[NJ][4], rbl[NJ][4];
            #pragma unroll
            for (int mi = 0; mi < MI; ++mi) {
                uint32_t aaddr = base + (uint32_t)((a_row + mi * 16) * LDS_ + kk + a_col) * 2;
                ldm4(aaddr, ra[mi]);
                ldm4(aaddr + MT * LDS_ * 2, rl[mi]);
            }
            #pragma unroll
            for (int nj = 0; nj < NJ; ++nj) {
                uint32_t baddr = base + (uint32_t)(2 * MT * LDS_ + (b_row + nj * 16) * LDS_ + kk + b_col) * 2;
                ldm4(baddr, rbh[nj]);
                ldm4(baddr + NT * LDS_ * 2, rbl[nj]);
            }
            #pragma unroll
            for (int mi = 0; mi < MI; ++mi) {
                #pragma unroll
                for (int b8 = 0; b8 < NJ * 2; ++b8) {
                    const uint32_t* bh = &rbh[b8 >> 1][(b8 & 1) * 2];
                    const uint32_t* bl = &rbl[b8 >> 1][(b8 & 1) * 2];
                    mma16816(acc[mi][b8], ra[mi], bh);   // hi*hi
                    mma16816(acc[mi][b8], ra[mi], bl);   // hi*lo
                    mma16816(acc[mi][b8], rl[mi], bh);   // lo*hi
                }
            }
        }
        __syncthreads();
    }
}

// ---------------------------------------------------------------------------
// Setup kernels
// ---------------------------------------------------------------------------
__global__ void init_state_kernel() {
    int idx = blockIdx.x * blockDim.x + threadIdx.x;
    if (idx == 0) g_arrive = 0u;
    if (idx < N_ * H_) {
        g_h_hi[0][idx] = __float2half_rn(0.0f);
        g_h_lo[0][idx] = __float2half_rn(0.0f);
        g_c[idx] = 0.0f;
    }
}

__global__ void conv_x_kernel(const float* __restrict__ X) {
    size_t base = ((size_t)blockIdx.x * blockDim.x + threadIdx.x) * 4;
    if (base < (size_t)M_ * KDIM) {
        float4 v = *(const float4*)(X + base);
        __half h0, l0, h1, l1, h2, l2, h3, l3;
        f2split(v.x, h0, l0); f2split(v.y, h1, l1);
        f2split(v.z, h2, l2); f2split(v.w, h3, l3);
        gX_hi[base + 0] = h0; gX_hi[base + 1] = h1; gX_hi[base + 2] = h2; gX_hi[base + 3] = h3;
        gX_lo[base + 0] = l0; gX_lo[base + 1] = l1; gX_lo[base + 2] = l2; gX_lo[base + 3] = l3;
    }
}

__global__ void conv_w_kernel(const float* __restrict__ Wih,
                              const float* __restrict__ Whh,
                              const float* __restrict__ bih,
                              const float* __restrict__ bhh) {
    int jp = blockIdx.x;                 // interleaved dst row 0..2047
    int gate = jp & 3, h = jp >> 2;
    int j = gate * H_ + h;               // source row
    const float* si = Wih + (size_t)j * KDIM;
    const float* sh = Whh + (size_t)j * KDIM;
    for (int k = threadIdx.x; k < KDIM; k += blockDim.x) {
        __half hi, lo;
        f2split(si[k], hi, lo);
        gWih_hi[(size_t)jp * KDIM + k] = hi; gWih_lo[(size_t)jp * KDIM + k] = lo;
        f2split(sh[k], hi, lo);
        gWhh_hi[(size_t)jp * KDIM + k] = hi; gWhh_lo[(size_t)jp * KDIM + k] = lo;
    }
    if (threadIdx.x == 0) g_biasI[jp] = bih[j] + bhh[j];
}

// ---------------------------------------------------------------------------
// x_gates GEMM: 128x128 tile, grid (16, 500), 2-stage, 2 CTAs/SM.
// ---------------------------------------------------------------------------
#define XG_STAGE ((2*128*LDS_ + 2*128*LDS_) * 2)         // 40960 B
#define XG_SMEM  (XG_STAGE * 2)                          // 81920 B

__global__ __launch_bounds__(256, 2)
void xg_mma_kernel() {
    extern __shared__ __half smem[];
    const uint32_t sb = smem_u32_of(smem);
    __shared__ float bias_s[128];
    const int tid = threadIdx.x;
    const int j0 = blockIdx.x * 128;
    const int m0 = blockIdx.y * 128;
    if (tid < 128) bias_s[tid] = g_biasI[j0 + tid];

    float acc[4][4][4];
    #pragma unroll
    for (int a = 0; a < 4; ++a)
        #pragma unroll
        for (int b = 0; b < 4; ++b)
            #pragma unroll
            for (int d = 0; d < 4; ++d) acc[a][b][d] = 0.0f;

    mma_mainloop<4, 2, 2>(sb,
        gX_hi   + (size_t)m0 * KDIM, gX_lo   + (size_t)m0 * KDIM,
        gWih_hi + (size_t)j0 * KDIM, gWih_lo + (size_t)j0 * KDIM,
        acc, tid);

    const int lane = tid & 31, wid = tid >> 5;
    const int mw = (wid & 1) * 64, nw = (wid >> 1) * 32;
    #pragma unroll
    for (int mi = 0; mi < 4; ++mi) {
        #pragma unroll
        for (int h2 = 0; h2 < 2; ++h2) {
            const int r = m0 + mw + mi * 16 + (lane >> 2) + h2 * 8;
            float* dst = g_xg + (size_t)r * G_ + j0;
            #pragma unroll
            for (int ni = 0; ni < 4; ++ni) {
                const int cc = nw + ni * 8 + (lane & 3) * 2;
                float2 v = make_float2(acc[mi][ni][h2 * 2 + 0] + bias_s[cc],
                                       acc[mi][ni][h2 * 2 + 1] + bias_s[cc + 1]);
                *(float2*)(dst + cc) = v;
            }
        }
    }
}

// ---------------------------------------------------------------------------
// Grid-wide barrier (128 CTAs, all co-resident at 1 CTA/SM)
// ---------------------------------------------------------------------------
__device__ __forceinline__ void grid_barrier(int tid, unsigned target) {
    __threadfence();
    __syncthreads();
    if (tid == 0) {
        atomicAdd(&g_arrive, 1u);
        unsigned v;
        do {
            asm volatile("ld.volatile.global.u32 %0, [%1];" : "=r"(v) : "l"(&g_arrive));
        } while (v < target);
        __threadfence();
    }
    __syncthreads();
}

// ---------------------------------------------------------------------------
// Persistent recurrent kernel. Grid (32, 4) = 128 CTAs, 1 CTA/SM.
// CTA owns: W slice (64 interleaved gate cols x 512, hi+lo) RESIDENT in smem
// for all 100 steps, and 160 sequence rows. Per step: 3-stage cp.async h
// pipeline (only 20KB/chunk streams), MMA, fused cell update, grid barrier.
// Warp layout: 2 (m, 80 rows: MI=5) x 4 (n, 16 cols: NJ=1).
// ---------------------------------------------------------------------------
__global__ __launch_bounds__(256, 1)
void lstm_persistent_kernel(float* __restrict__ out) {
    extern __shared__ __half smem[];
    const uint32_t sb = smem_u32_of(smem);
    const int tid = threadIdx.x;
    const int jb = blockIdx.x;            // 0..31
    const int nc = blockIdx.y;            // 0..3
    const int j0 = jb * 64;               // interleaved gate-col base
    const int hb = jb * 16;               // h-col base
    const int n0 = nc * ROWS_P;           // row base
    const int lane = tid & 31, wid = tid >> 5;
    const int wn = wid & 3, wm = wid >> 2;

    // ---- load resident W slice: 64 rows x 512, stride 520, hi+lo ----
    {
        const __half* Wh = gWhh_hi + (size_t)j0 * KDIM;
        const __half* Wl = gWhh_lo + (size_t)j0 * KDIM;
        #pragma unroll 4
        for (int u = tid; u < 64 * 64; u += 256) {
            int r = u >> 6, c = (u & 63) * 8;
            *(uint4*)&smem[SM_WHI + r * WSTRIDE + c] = *(const uint4*)&Wh[(size_t)r * KDIM + c];
            *(uint4*)&smem[SM_WLO + r * WSTRIDE + c] = *(const uint4*)&Wl[(size_t)r * KDIM + c];
        }
    }
    __syncthreads();

    // ldmatrix lane addressing
    const int a_row = wm * 80 + (lane & 15);
    const int a_col = (lane >> 4) * 8;
    const int b_row = wn * 16 + ((lane >> 4) << 3) + (lane & 7);
    const int b_col = ((lane >> 3) & 1) * 8;
    const uint32_t wb_hi = sb + (uint32_t)(SM_WHI + b_row * WSTRIDE + b_col) * 2;
    const uint32_t wb_lo = sb + (uint32_t)(SM_WLO + b_row * WSTRIDE + b_col) * 2;
    const uint32_t hstg = sb + (uint32_t)SM_HST * 2;
    float* Cs = (float*)(smem + SM_HST);   // C staging reuses h-stage region

    #pragma unroll 1
    for (int t = 0; t < T_; ++t) {
        const int cur = t & 1, nxt = cur ^ 1;
        const __half* Hh = g_h_hi[cur] + (size_t)n0 * H_;
        const __half* Hl = g_h_lo[cur] + (size_t)n0 * H_;

        float acc[5][2][4];
        #pragma unroll
        for (int a = 0; a < 5; ++a)
            #pragma unroll
            for (int b = 0; b < 2; ++b)
                #pragma unroll
                for (int d = 0; d < 4; ++d) acc[a][b][d] = 0.0f;

        // h chunk loader: 160 rows x 32 k (hi+lo), stride 40
        #define LOADH(stage, kc) do {                                          \
            uint32_t dbase = hstg + (uint32_t)((stage) * HSTAGE_E) * 2;        \
            _Pragma("unroll")                                                  \
            for (int u = tid; u < 640; u += 256) {                             \
                int r_ = u >> 2, cg_ = (u & 3) * 8;                            \
                uint32_t d_ = dbase + (uint32_t)(r_ * LDS_ + cg_) * 2;         \
                size_t go_ = (size_t)r_ * H_ + (kc) + cg_;                     \
                cp16(d_,            Hh + go_);                                 \
                cp16(d_ + 6400 * 2, Hl + go_);                                 \
            }                                                                  \
        } while (0)

        LOADH(0, 0);  cp_commit();
        LOADH(1, CH); cp_commit();

        #pragma unroll 1
        for (int c = 0; c < NCHUNK; ++c) {
            if (c + 2 < NCHUNK) LOADH((c + 2) % 3, (c + 2) * CH);
            cp_commit();
            cp_wait<2>();
            __syncthreads();

            const uint32_t base = hstg + (uint32_t)((c % 3) * HSTAGE_E) * 2;
            const int kc = c * CH;
            #pragma unroll
            for (int kk = 0; kk < CH; kk += 16) {
                uint32_t ra[5][4], rl[5][4], rbh[4], rbl[4];
                #pragma unroll
                for (int mi = 0; mi < 5; ++mi) {
                    uint32_t aaddr = base + (uint32_t)((a_row + mi * 16) * LDS_ + kk + a_col) * 2;
                    ldm4(aaddr, ra[mi]);
                    ldm4(aaddr + 6400 * 2, rl[mi]);
                }
                ldm4(wb_hi + (uint32_t)(kc + kk) * 2, rbh);
                ldm4(wb_lo + (uint32_t)(kc + kk) * 2, rbl);
                #pragma unroll
                for (int mi = 0; mi < 5; ++mi) {
                    #pragma unroll
                    for (int b8 = 0; b8 < 2; ++b8) {
                        const uint32_t* bh = &rbh[b8 * 2];
                        const uint32_t* bl = &rbl[b8 * 2];
                        mma16816(acc[mi][b8], ra[mi], bh);   // hi*hi
                        mma16816(acc[mi][b8], ra[mi], bl);   // hi*lo
                        mma16816(acc[mi][b8], rl[mi], bh);   // lo*hi
                    }
                }
            }
            __syncthreads();
        }
        #undef LOADH

        // stage C tile [160][64] (stride 68) in smem
        #pragma unroll
        for (int mi = 0; mi < 5; ++mi) {
            #pragma unroll
            for (int b8 = 0; b8 < 2; ++b8) {
                const int r = wm * 80 + mi * 16 + (lane >> 2);
                const int cc = wn * 16 + b8 * 8 + (lane & 3) * 2;
                *(float2*)&Cs[r * 68 + cc]       = make_float2(acc[mi][b8][0], acc[mi][b8][1]);
                *(float2*)&Cs[(r + 8) * 68 + cc] = make_float2(acc[mi][b8][2], acc[mi][b8][3]);
            }
        }
        __syncthreads();

        // fused LSTM cell update: 10 cells/thread
        const bool last = (t == T_ - 1);
        const int hl = tid & 15;
        const int rg = tid >> 4;
        #pragma unroll
        for (int e = 0; e < 10; ++e) {
            const int r = rg + e * 16;
            const int gn = n0 + r;
            float4 cg = *(const float4*)&Cs[r * 68 + hl * 4];
            float4 xv = *(const float4*)(g_xg + ((size_t)gn * T_ + t) * G_ + j0 + hl * 4);
            float ig = cg.x + xv.x, fg = cg.y + xv.y;
            float gg = cg.z + xv.z, og = cg.w + xv.w;

            float is = 1.0f / (1.0f + __expf(-ig));
            float fs = 1.0f / (1.0f + __expf(-fg));
            float gt = tanhf(gg);
            float os = 1.0f / (1.0f + __expf(-og));

            const size_t ci = (size_t)gn * H_ + hb + hl;
            float c = fs * g_c[ci] + is * gt;
            g_c[ci] = c;
            float hv = os * tanhf(c);
            if (last) {
                out[ci] = hv;
            } else {
                __half hi, lo;
                f2split(hv, hi, lo);
                g_h_hi[nxt][ci] = hi;
                g_h_lo[nxt][ci] = lo;
            }
        }

        if (t + 1 < T_)
            grid_barrier(tid, (unsigned)NCTA_P * (unsigned)(t + 1));
    }
}

// ---------------------------------------------------------------------------
// Launch
// ---------------------------------------------------------------------------
extern "C" void kernel_launch(void* const* d_in, const int* in_sizes, int n_in,
                              void* d_out, int out_size)
{
    const float* X   = (const float*)d_in[0];   // [B,Q,T,D] == [N*T, D]
    const float* Wih = (const float*)d_in[1];   // [4H, D]
    const float* Whh = (const float*)d_in[2];   // [4H, H]
    const float* bih = (const float*)d_in[3];   // [4H]
    const float* bhh = (const float*)d_in[4];   // [4H]
    float* out = (float*)d_out;                 // [B,Q,H] == [N, H]

    cudaFuncSetAttribute(xg_mma_kernel,          cudaFuncAttributeMaxDynamicSharedMemorySize, XG_SMEM);
    cudaFuncSetAttribute(lstm_persistent_kernel, cudaFuncAttributeMaxDynamicSharedMemorySize, SMEM_P_BYTES);

    init_state_kernel<<<(N_ * H_ + 255) / 256, 256>>>();
    conv_x_kernel<<<(int)(((size_t)M_ * KDIM / 4 + 255) / 256), 256>>>(X);
    conv_w_kernel<<<G_, 256>>>(Wih, Whh, bih, bhh);

    xg_mma_kernel<<<dim3(G_ / 128, M_ / 128), 256, XG_SMEM>>>();

    lstm_persistent_kernel<<<dim3(32, 4), 256, SMEM_P_BYTES>>>(out);
}